// round 1
// baseline (speedup 1.0000x reference)
#include <cuda_runtime.h>
#include <cuda_bf16.h>

// Problem constants (from reference): B=524288, D=256, C=1000. D is hardcoded
// (thread-per-element layout); B and C are derived from in_sizes.
#define D_DIM 256
#define C_MAX 1024          // capacity for class count (actual C=1000)
#define BUCKET_CAP 2048     // per-class row-index capacity (expected ~524, max ~650)

// Scratch (allocation-free: __device__ globals)
__device__ int   g_counts[C_MAX];
__device__ int   g_bucket[C_MAX * BUCKET_CAP];
__device__ float g_loss_sum;
__device__ int   g_n_present;
__device__ int   g_is64;

// ---------------------------------------------------------------------------
// Kernel 0: zero scratch + detect label dtype (int64 vs int32 storage)
// ---------------------------------------------------------------------------
__global__ void init_detect_kernel(const void* __restrict__ lraw, int B, int C) {
    int tid = threadIdx.x;
    for (int i = tid; i < C; i += blockDim.x) g_counts[i] = 0;
    if (tid == 0) { g_loss_sum = 0.0f; g_n_present = 0; }

    __shared__ int s_bad;
    if (tid == 0) s_bad = 0;
    __syncthreads();

    const long long* l64 = (const long long*)lraw;
    int n = (B < 1024) ? B : 1024;
    int bad = 0;
    for (int i = tid; i < n; i += blockDim.x) {
        long long v = l64[i];
        if (v < 0 || v >= (long long)C) bad = 1;
    }
    if (bad) atomicOr(&s_bad, 1);
    __syncthreads();
    if (tid == 0) g_is64 = s_bad ? 0 : 1;
}

// ---------------------------------------------------------------------------
// Kernel 1: bin row indices by class (int atomics only)
// ---------------------------------------------------------------------------
__global__ void bin_kernel(const void* __restrict__ lraw, int B) {
    int i = blockIdx.x * blockDim.x + threadIdx.x;
    if (i >= B) return;
    int c;
    if (g_is64) c = (int)((const long long*)lraw)[i];
    else        c = ((const int*)lraw)[i];
    int pos = atomicAdd(&g_counts[c], 1);
    if (pos < BUCKET_CAP) g_bucket[c * BUCKET_CAP + pos] = i;
}

// ---------------------------------------------------------------------------
// Block reduce (256 threads = 8 warps)
// ---------------------------------------------------------------------------
__device__ __forceinline__ float block_reduce_256(float v, float* s_red, int tid) {
    #pragma unroll
    for (int o = 16; o > 0; o >>= 1) v += __shfl_down_sync(0xffffffffu, v, o);
    if ((tid & 31) == 0) s_red[tid >> 5] = v;
    __syncthreads();
    if (tid < 32) {
        v = (tid < 8) ? s_red[tid] : 0.0f;
        #pragma unroll
        for (int o = 4; o > 0; o >>= 1) v += __shfl_down_sync(0xffffffffu, v, o);
        if (tid == 0) s_red[0] = v;
    }
    __syncthreads();
    float r = s_red[0];
    __syncthreads();   // protect s_red for reuse
    return r;
}

// ---------------------------------------------------------------------------
// Kernel 2: one block per class. Gather x rows for this class, mean,
// momentum update, L2-normalize, squared distance to center_skt,
// accumulate masked loss.
// ---------------------------------------------------------------------------
__global__ void __launch_bounds__(256) class_kernel(
    const float* __restrict__ x,
    const float* __restrict__ cimg,
    const float* __restrict__ cskt)
{
    const int c   = blockIdx.x;
    const int tid = threadIdx.x;

    const int count = g_counts[c];
    if (count <= 0) return;   // absent class: contributes nothing to loss

    const int m = (count < BUCKET_CAP) ? count : BUCKET_CAP;
    const int* __restrict__ bucket = &g_bucket[c * BUCKET_CAP];

    __shared__ int   s_rows[256];
    __shared__ float s_red[32];

    float acc = 0.0f;
    for (int base = 0; base < m; base += 256) {
        const int chunk = min(256, m - base);
        __syncthreads();
        if (tid < chunk) s_rows[tid] = bucket[base + tid];
        __syncthreads();

        int j = 0;
        for (; j + 4 <= chunk; j += 4) {
            const int r0 = s_rows[j + 0];
            const int r1 = s_rows[j + 1];
            const int r2 = s_rows[j + 2];
            const int r3 = s_rows[j + 3];
            // 4 independent coalesced loads -> MLP=4 per thread
            float v0 = __ldg(&x[(size_t)r0 * D_DIM + tid]);
            float v1 = __ldg(&x[(size_t)r1 * D_DIM + tid]);
            float v2 = __ldg(&x[(size_t)r2 * D_DIM + tid]);
            float v3 = __ldg(&x[(size_t)r3 * D_DIM + tid]);
            acc += v0; acc += v1; acc += v2; acc += v3;
        }
        for (; j < chunk; ++j) {
            acc += __ldg(&x[(size_t)s_rows[j] * D_DIM + tid]);
        }
    }
    __syncthreads();

    const float mean = acc / (float)count;
    const float ci   = cimg[c * D_DIM + tid];
    const float upd  = ci * 0.9f + mean * 0.1f;

    // L2 norm over D
    const float nrm2 = block_reduce_256(upd * upd, s_red, tid);
    const float inv_norm = 1.0f / sqrtf(nrm2);

    const float v  = upd * inv_norm;
    const float d  = v - cskt[c * D_DIM + tid];
    const float sq = block_reduce_256(d * d, s_red, tid);

    if (tid == 0) {
        atomicAdd(&g_loss_sum, sq);
        atomicAdd(&g_n_present, 1);
    }
}

// ---------------------------------------------------------------------------
// Kernel 3: final scalar
// ---------------------------------------------------------------------------
__global__ void finish_kernel(float* __restrict__ out) {
    int n = g_n_present;
    if (n < 1) n = 1;
    out[0] = g_loss_sum / (float)n;
}

// ---------------------------------------------------------------------------
extern "C" void kernel_launch(void* const* d_in, const int* in_sizes, int n_in,
                              void* d_out, int out_size) {
    const float* x    = (const float*)d_in[0];
    const void*  lraw = d_in[1];
    const float* cimg = (const float*)d_in[2];
    const float* cskt = (const float*)d_in[3];
    float* out = (float*)d_out;

    const int B = in_sizes[1];               // 524288
    const int C = in_sizes[2] / D_DIM;       // 1000

    init_detect_kernel<<<1, 256>>>(lraw, B, C);
    bin_kernel<<<(B + 255) / 256, 256>>>(lraw, B);
    class_kernel<<<C, 256>>>(x, cimg, cskt);
    finish_kernel<<<1, 1>>>(out);
}

// round 4
// speedup vs baseline: 1.0319x; 1.0319x over previous
#include <cuda_runtime.h>
#include <cuda_bf16.h>

// B=524288, D=256, C=1000 (D hardcoded for thread-per-element layout).
#define D_DIM 256
#define C_MAX 1024
#define BUCKET_CAP 2048   // expected ~524/class, Poisson max ~650

// Scratch: __device__ globals (zero-initialized at load; self-cleaned per run).
__device__ int   g_counts[C_MAX];
__device__ int   g_bucket[C_MAX * BUCKET_CAP];
__device__ float g_loss_sum;
__device__ int   g_n_present;
__device__ int   g_done;

// ---------------------------------------------------------------------------
// Kernel 1: bin row indices by class. Each block independently (and
// deterministically) detects whether labels are stored as int64 or int32 by
// range-checking the first 1024 words interpreted as int64.
// ---------------------------------------------------------------------------
__global__ void __launch_bounds__(256) bin_kernel(const void* __restrict__ lraw,
                                                  int B, int C) {
    __shared__ int s_bad;
    const int tid = threadIdx.x;
    if (tid == 0) s_bad = 0;
    __syncthreads();

    const long long* __restrict__ l64 = (const long long*)lraw;
    const int n = (B < 1024) ? B : 1024;
    int bad = 0;
    for (int i = tid; i < n; i += 256) {
        const long long v = l64[i];
        if (v < 0 || v >= (long long)C) bad = 1;
    }
    if (bad) atomicOr(&s_bad, 1);
    __syncthreads();
    const bool is64 = (s_bad == 0);

    const int stride = gridDim.x * blockDim.x;
    const int* __restrict__ l32 = (const int*)lraw;
    for (int i = blockIdx.x * blockDim.x + tid; i < B; i += stride) {
        const int c = is64 ? (int)l64[i] : l32[i];
        const int pos = atomicAdd(&g_counts[c], 1);
        if (pos < BUCKET_CAP) g_bucket[c * BUCKET_CAP + pos] = i;
    }
}

// ---------------------------------------------------------------------------
// Block reduce over 256 threads (8 warps)
// ---------------------------------------------------------------------------
__device__ __forceinline__ float block_reduce_256(float v, float* s_red, int tid) {
    #pragma unroll
    for (int o = 16; o > 0; o >>= 1) v += __shfl_down_sync(0xffffffffu, v, o);
    if ((tid & 31) == 0) s_red[tid >> 5] = v;
    __syncthreads();
    if (tid < 32) {
        v = (tid < 8) ? s_red[tid] : 0.0f;
        #pragma unroll
        for (int o = 4; o > 0; o >>= 1) v += __shfl_down_sync(0xffffffffu, v, o);
        if (tid == 0) s_red[0] = v;
    }
    __syncthreads();
    const float r = s_red[0];
    __syncthreads();
    return r;
}

// ---------------------------------------------------------------------------
// Kernel 2: one block per class. float4 gather (4 independent LDG.128 per
// thread in flight), mean, momentum update, L2-normalize, squared distance,
// masked-mean loss. Last finishing block writes the scalar output and resets
// all shared scratch (self-cleaning for graph replay).
// ---------------------------------------------------------------------------
__global__ void __launch_bounds__(256) class_kernel(
    const float* __restrict__ x,
    const float* __restrict__ cimg,
    const float* __restrict__ cskt,
    float* __restrict__ out)
{
    const int c   = blockIdx.x;
    const int tid = threadIdx.x;
    const int q   = tid >> 6;        // row slot 0..3
    const int ds  = tid & 63;        // float4 index within a 256-float row

    // NOTE: s_part is accessed as float4 -> must be explicitly 16B-aligned.
    // (R3 crash: adding s_count shifted s_part to a 4B-aligned offset ->
    //  STS.128 misaligned-address trap.)
    __shared__ __align__(16) float s_part[4 * 256];
    __shared__ __align__(16) int   s_rows[512];
    __shared__ float s_red[32];
    __shared__ int   s_count;

    // Single-reader broadcast: tid 0 reads AND resets the counter; everyone
    // else gets the value after the barrier.
    if (tid == 0) {
        s_count = g_counts[c];
        g_counts[c] = 0;             // self-clean for next graph replay
    }
    __syncthreads();
    const int count = s_count;

    if (count > 0) {
        const int m = (count < BUCKET_CAP) ? count : BUCKET_CAP;
        const int* __restrict__ bucket = &g_bucket[c * BUCKET_CAP];

        float4 acc = make_float4(0.f, 0.f, 0.f, 0.f);

        for (int base = 0; base < m; base += 512) {
            const int chunk = (m - base < 512) ? (m - base) : 512;
            __syncthreads();
            for (int t = tid; t < chunk; t += 256) s_rows[t] = bucket[base + t];
            __syncthreads();

            int j = 0;
            for (; j + 16 <= chunk; j += 16) {
                const int r0 = s_rows[j      + q];
                const int r1 = s_rows[j + 4  + q];
                const int r2 = s_rows[j + 8  + q];
                const int r3 = s_rows[j + 12 + q];
                const float4 v0 = __ldg((const float4*)(x + (size_t)r0 * D_DIM) + ds);
                const float4 v1 = __ldg((const float4*)(x + (size_t)r1 * D_DIM) + ds);
                const float4 v2 = __ldg((const float4*)(x + (size_t)r2 * D_DIM) + ds);
                const float4 v3 = __ldg((const float4*)(x + (size_t)r3 * D_DIM) + ds);
                acc.x += v0.x + v1.x + v2.x + v3.x;
                acc.y += v0.y + v1.y + v2.y + v3.y;
                acc.z += v0.z + v1.z + v2.z + v3.z;
                acc.w += v0.w + v1.w + v2.w + v3.w;
            }
            for (; j < chunk; j += 4) {
                const int idx = j + q;
                if (idx < chunk) {
                    const int r = s_rows[idx];
                    const float4 v = __ldg((const float4*)(x + (size_t)r * D_DIM) + ds);
                    acc.x += v.x; acc.y += v.y; acc.z += v.z; acc.w += v.w;
                }
            }
        }

        // Combine the 4 row-slot partial sums across q via smem.
        __syncthreads();
        *((float4*)(s_part + q * 256) + ds) = acc;
        __syncthreads();
        const float sum = s_part[0 * 256 + tid] + s_part[1 * 256 + tid] +
                          s_part[2 * 256 + tid] + s_part[3 * 256 + tid];

        const float mean = sum / (float)count;
        const float ci   = cimg[c * D_DIM + tid];
        const float upd  = fmaf(ci, 0.9f, mean * 0.1f);

        const float nrm2 = block_reduce_256(upd * upd, s_red, tid);
        const float v    = upd * rsqrtf(nrm2);

        const float d  = v - cskt[c * D_DIM + tid];
        const float sq = block_reduce_256(d * d, s_red, tid);

        if (tid == 0) {
            atomicAdd(&g_loss_sum, sq);
            atomicAdd(&g_n_present, 1);
        }
    }

    // Completion protocol: last block finalizes the scalar and resets scratch.
    if (tid == 0) {
        __threadfence();
        const int t = atomicAdd(&g_done, 1);
        if (t == (int)gridDim.x - 1) {
            const float ls = atomicAdd(&g_loss_sum, 0.0f);   // coherent read
            int np = atomicAdd(&g_n_present, 0);
            if (np < 1) np = 1;
            out[0] = ls / (float)np;
            g_loss_sum  = 0.0f;
            g_n_present = 0;
            g_done      = 0;
        }
    }
}

// ---------------------------------------------------------------------------
extern "C" void kernel_launch(void* const* d_in, const int* in_sizes, int n_in,
                              void* d_out, int out_size) {
    const float* x    = (const float*)d_in[0];
    const void*  lraw = d_in[1];
    const float* cimg = (const float*)d_in[2];
    const float* cskt = (const float*)d_in[3];
    float* out = (float*)d_out;

    const int B = in_sizes[1];           // 524288
    const int C = in_sizes[2] / D_DIM;   // 1000

    bin_kernel<<<1024, 256>>>(lraw, B, C);
    class_kernel<<<C, 256>>>(x, cimg, cskt, out);
}

// round 5
// speedup vs baseline: 1.4696x; 1.4241x over previous
#include <cuda_runtime.h>
#include <cuda_bf16.h>

// B=524288, D=256, C=1000 (D hardcoded for thread-per-element layout).
#define D_DIM 256
#define C_MAX 1024
#define BUCKET_CAP 2048     // expected ~524/class, Poisson max ~650
#define CNT_PAD 32          // one counter per 128B line -> distinct LTS slices
#define BIN_CHUNK 4096      // labels per bin block

// Scratch: __device__ globals (zero-initialized at load; self-cleaned per run).
__device__ int   g_counts[C_MAX * CNT_PAD];   // padded counters (128 KB)
__device__ int   g_bucket[C_MAX * BUCKET_CAP];
__device__ float g_loss_sum;
__device__ int   g_n_present;
__device__ int   g_done;

// ---------------------------------------------------------------------------
// Kernel 1: bin row indices by class, two-level.
//   Phase A: decode labels once into smem + smem histogram (fast atomics).
//   Phase B: ONE padded global atomic per (block,class) reserves a bucket
//            range (128K atomics on 1000 distinct cache lines, vs 524K on 32).
//   Phase C: write row indices at reserved offsets (semi-contiguous stores).
// Dtype (int64 vs int32 storage) detected per-block by range-checking the
// first 1024 words as int64 — deterministic, L2-hot.
// ---------------------------------------------------------------------------
__global__ void __launch_bounds__(1024) bin_kernel(const void* __restrict__ lraw,
                                                   int B, int C) {
    __shared__ unsigned short s_lab[BIN_CHUNK];   // 8 KB
    __shared__ int s_hist[C_MAX];                 // 4 KB (hist, then cursor)
    __shared__ int s_base[C_MAX];                 // 4 KB
    __shared__ int s_bad;

    const int tid = threadIdx.x;
    if (tid == 0) s_bad = 0;
    for (int i = tid; i < C_MAX; i += 1024) s_hist[i] = 0;
    __syncthreads();

    const long long* __restrict__ l64 = (const long long*)lraw;
    const int* __restrict__       l32 = (const int*)lraw;

    {
        const int n = (B < 1024) ? B : 1024;
        int bad = 0;
        for (int i = tid; i < n; i += 1024) {
            const long long v = l64[i];
            if (v < 0 || v >= (long long)C) bad = 1;
        }
        if (bad) atomicOr(&s_bad, 1);
    }
    __syncthreads();
    const bool is64 = (s_bad == 0);

    const int start = blockIdx.x * BIN_CHUNK;
    const int end   = (start + BIN_CHUNK < B) ? (start + BIN_CHUNK) : B;
    const int cnt   = end - start;

    // Phase A: decode + local histogram
    for (int i = tid; i < cnt; i += 1024) {
        const int c = is64 ? (int)l64[start + i] : l32[start + i];
        s_lab[i] = (unsigned short)c;
        atomicAdd(&s_hist[c], 1);
    }
    __syncthreads();

    // Phase B: reserve global ranges; reset hist for reuse as cursor
    for (int c = tid; c < C; c += 1024) {
        const int h = s_hist[c];
        s_base[c] = h ? atomicAdd(&g_counts[c * CNT_PAD], h) : 0;
        s_hist[c] = 0;
    }
    __syncthreads();

    // Phase C: scatter row indices into reserved (contiguous) slots
    for (int i = tid; i < cnt; i += 1024) {
        const int c   = s_lab[i];
        const int pos = s_base[c] + atomicAdd(&s_hist[c], 1);
        if (pos < BUCKET_CAP) g_bucket[c * BUCKET_CAP + pos] = start + i;
    }
}

// ---------------------------------------------------------------------------
// Block reduce over 256 threads (8 warps)
// ---------------------------------------------------------------------------
__device__ __forceinline__ float block_reduce_256(float v, float* s_red, int tid) {
    #pragma unroll
    for (int o = 16; o > 0; o >>= 1) v += __shfl_down_sync(0xffffffffu, v, o);
    if ((tid & 31) == 0) s_red[tid >> 5] = v;
    __syncthreads();
    if (tid < 32) {
        v = (tid < 8) ? s_red[tid] : 0.0f;
        #pragma unroll
        for (int o = 4; o > 0; o >>= 1) v += __shfl_down_sync(0xffffffffu, v, o);
        if (tid == 0) s_red[0] = v;
    }
    __syncthreads();
    const float r = s_red[0];
    __syncthreads();
    return r;
}

// ---------------------------------------------------------------------------
// Kernel 2: one block per class. float4 gather (4 independent LDG.128 per
// thread in flight), mean, momentum update, L2-normalize, squared distance,
// masked-mean loss. Last finishing block writes the scalar output and resets
// all shared scratch (self-cleaning for graph replay).
// ---------------------------------------------------------------------------
__global__ void __launch_bounds__(256) class_kernel(
    const float* __restrict__ x,
    const float* __restrict__ cimg,
    const float* __restrict__ cskt,
    float* __restrict__ out)
{
    const int c   = blockIdx.x;
    const int tid = threadIdx.x;
    const int q   = tid >> 6;        // row slot 0..3
    const int ds  = tid & 63;        // float4 index within a 256-float row

    __shared__ __align__(16) float s_part[4 * 256];
    __shared__ __align__(16) int   s_rows[512];
    __shared__ float s_red[32];
    __shared__ int   s_count;

    if (tid == 0) {
        s_count = g_counts[c * CNT_PAD];
        g_counts[c * CNT_PAD] = 0;   // self-clean for next graph replay
    }
    __syncthreads();
    const int count = s_count;

    if (count > 0) {
        const int m = (count < BUCKET_CAP) ? count : BUCKET_CAP;
        const int* __restrict__ bucket = &g_bucket[c * BUCKET_CAP];

        float4 acc = make_float4(0.f, 0.f, 0.f, 0.f);

        for (int base = 0; base < m; base += 512) {
            const int chunk = (m - base < 512) ? (m - base) : 512;
            __syncthreads();
            for (int t = tid; t < chunk; t += 256) s_rows[t] = bucket[base + t];
            __syncthreads();

            int j = 0;
            for (; j + 16 <= chunk; j += 16) {
                const int r0 = s_rows[j      + q];
                const int r1 = s_rows[j + 4  + q];
                const int r2 = s_rows[j + 8  + q];
                const int r3 = s_rows[j + 12 + q];
                const float4 v0 = __ldg((const float4*)(x + (size_t)r0 * D_DIM) + ds);
                const float4 v1 = __ldg((const float4*)(x + (size_t)r1 * D_DIM) + ds);
                const float4 v2 = __ldg((const float4*)(x + (size_t)r2 * D_DIM) + ds);
                const float4 v3 = __ldg((const float4*)(x + (size_t)r3 * D_DIM) + ds);
                acc.x += v0.x + v1.x + v2.x + v3.x;
                acc.y += v0.y + v1.y + v2.y + v3.y;
                acc.z += v0.z + v1.z + v2.z + v3.z;
                acc.w += v0.w + v1.w + v2.w + v3.w;
            }
            for (; j < chunk; j += 4) {
                const int idx = j + q;
                if (idx < chunk) {
                    const int r = s_rows[idx];
                    const float4 v = __ldg((const float4*)(x + (size_t)r * D_DIM) + ds);
                    acc.x += v.x; acc.y += v.y; acc.z += v.z; acc.w += v.w;
                }
            }
        }

        // Combine the 4 row-slot partial sums across q via smem.
        __syncthreads();
        *((float4*)(s_part + q * 256) + ds) = acc;
        __syncthreads();
        const float sum = s_part[0 * 256 + tid] + s_part[1 * 256 + tid] +
                          s_part[2 * 256 + tid] + s_part[3 * 256 + tid];

        const float mean = sum / (float)count;
        const float ci   = cimg[c * D_DIM + tid];
        const float upd  = fmaf(ci, 0.9f, mean * 0.1f);

        const float nrm2 = block_reduce_256(upd * upd, s_red, tid);
        const float v    = upd * rsqrtf(nrm2);

        const float d  = v - cskt[c * D_DIM + tid];
        const float sq = block_reduce_256(d * d, s_red, tid);

        if (tid == 0) {
            atomicAdd(&g_loss_sum, sq);
            atomicAdd(&g_n_present, 1);
        }
    }

    // Completion protocol: last block finalizes the scalar and resets scratch.
    if (tid == 0) {
        __threadfence();
        const int t = atomicAdd(&g_done, 1);
        if (t == (int)gridDim.x - 1) {
            const float ls = atomicAdd(&g_loss_sum, 0.0f);   // coherent read
            int np = atomicAdd(&g_n_present, 0);
            if (np < 1) np = 1;
            out[0] = ls / (float)np;
            g_loss_sum  = 0.0f;
            g_n_present = 0;
            g_done      = 0;
        }
    }
}

// ---------------------------------------------------------------------------
extern "C" void kernel_launch(void* const* d_in, const int* in_sizes, int n_in,
                              void* d_out, int out_size) {
    const float* x    = (const float*)d_in[0];
    const void*  lraw = d_in[1];
    const float* cimg = (const float*)d_in[2];
    const float* cskt = (const float*)d_in[3];
    float* out = (float*)d_out;

    const int B = in_sizes[1];           // 524288
    const int C = in_sizes[2] / D_DIM;   // 1000

    const int nb = (B + BIN_CHUNK - 1) / BIN_CHUNK;   // 128
    bin_kernel<<<nb, 1024>>>(lraw, B, C);
    class_kernel<<<C, 256>>>(x, cimg, cskt, out);
}